// round 13
// baseline (speedup 1.0000x reference)
#include <cuda_runtime.h>
#include <math.h>

typedef unsigned long long ull;

// ---------------------------------------------------------------------------
// Packed f32x2 helpers (convB only — measured fastest for L4)
// ---------------------------------------------------------------------------
__device__ __forceinline__ ull pk2(float lo, float hi) {
    ull r; asm("mov.b64 %0, {%1, %2};" : "=l"(r) : "f"(lo), "f"(hi)); return r;
}
__device__ __forceinline__ void upk2(ull v, float& lo, float& hi) {
    asm("mov.b64 {%0, %1}, %2;" : "=f"(lo), "=f"(hi) : "l"(v));
}
__device__ __forceinline__ void fma2(ull& d, ull a, ull b) {
    asm("fma.rn.f32x2 %0, %1, %2, %0;" : "+l"(d) : "l"(a), "l"(b));
}

// ---------------------------------------------------------------------------
// Intermediate activation buffers (device globals — no allocation allowed).
// ---------------------------------------------------------------------------
__device__ float g_a1[38880000];   // 256*3*15^4
__device__ float g_a2[15925248];   // 256*3*12^4
__device__ float g_a3[6718464];    // 256*4*9^4
__device__ float g_a4[1658880];    // 256*5*6^4
__device__ float g_a5[327680];     // 256*5*4^4  (== flattened [256,1280])

__host__ __device__ constexpr int slice_pitch(int s3) { return (s3 + 6) & ~1; }

// ===========================================================================
// convW: Winograd-F(3,4)-in-W conv (+bias+ReLU) for K=4 layers.
// Block = (b, t-chunk), thread = (t_local, d, h) — identical blocking to
// convS. Per staged slice, each W-row is transformed ONCE (V = B^T d) into
// s_v; weights transformed ONCE per block (U = A g) into s_u. The hot loop
// accumulates m[co][tile][0..5] += U*V (6 muls per 3 outputs instead of 12).
// Output transform y = G^T m applied once at the end.
//
//   U0=g0; U1=g0+g1+g2+g3; U2=g0-g1+g2-g3; U3=g0+2g1+4g2+8g3;
//   U4=g0-2g1+4g2-8g3; U5=g3
//   V0=4d0-5d2+d4; V1=-4d1-4d2+d3+d4; V2=4d1-4d2-d3+d4;
//   V3=-2d1-d2+2d3+d4; V4=2d1-d2-2d3+d4; V5=4d1-5d3+d5
//   y0=m0/4-(m1+m2)/6+(m3+m4)/24; y1=(m2-m1)/6+(m3-m4)/12;
//   y2=-(m1+m2)/6+(m3+m4)/6+m5
// ===========================================================================
template<int CIN, int COUT, int K, int S, int TLOC, int NTHR, int MINB>
__global__ void __launch_bounds__(NTHR, MINB)
convW(const float* __restrict__ in, float* __restrict__ out,
      const float* __restrict__ w, const float* __restrict__ bias)
{
    static_assert(K == 4, "convW requires K=4");
    constexpr int O = S - K + 1;
    static_assert(O % 3 == 0, "convW requires O divisible by 3");
    constexpr int NT = O / 3;                  // F(3,4) tiles per W-row
    constexpr int TCH = O / TLOC, NST = TLOC + K - 1;
    constexpr int S2 = S * S, S3 = S2 * S, S4 = S3 * S;
    constexpr int O2 = O * O, O3 = O2 * O;
    constexpr int NACT = TLOC * O2;
    constexpr int VSTR = NT * 6 + 1;           // odd pitch -> conflict-free
    constexpr int NTAP = CIN * K * K * K;      // (ci,kt,kd,kh)

    __shared__ float s_v[S2 * VSTR];
    __shared__ float s_u[NTAP * COUT * 6];

    const int bt = blockIdx.x, tch = bt % TCH, b = bt / TCH;
    const int t0 = tch * TLOC, tid = threadIdx.x;

    // ---- weight transform U = A·g, once per block ----
    for (int i = tid; i < NTAP * COUT; i += NTHR) {
        const int tap = i / COUT, co = i - tap * COUT;
        const int kh = tap % K;  const int r1 = tap / K;
        const int kd = r1 % K;   const int r2 = r1 / K;
        const int kt = r2 % K;   const int ci = r2 / K;
        const float* gp = w + ((((co * CIN + ci) * K + kt) * K + kd) * K + kh) * K;
        const float g0 = gp[0], g1 = gp[1], g2 = gp[2], g3 = gp[3];
        float* up = s_u + (size_t)i * 6;
        up[0] = g0;
        up[1] = g0 + g1 + g2 + g3;
        up[2] = g0 - g1 + g2 - g3;
        up[3] = g0 + 2.0f * g1 + 4.0f * g2 + 8.0f * g3;
        up[4] = g0 - 2.0f * g1 + 4.0f * g2 - 8.0f * g3;
        up[5] = g3;
    }

    const int tl = tid / O2, rem = tid - tl * O2, dd = rem / O, hh = rem - dd * O;
    const bool act = tid < NACT;

    float m[COUT][NT][6];
#pragma unroll
    for (int c = 0; c < COUT; c++)
#pragma unroll
        for (int nt = 0; nt < NT; nt++)
#pragma unroll
            for (int j = 0; j < 6; j++) m[c][nt][j] = 0.0f;

#pragma unroll 1
    for (int ci = 0; ci < CIN; ci++) {
#pragma unroll 1
        for (int s = 0; s < NST; s++) {
            __syncthreads();
            // ---- stage + input transform: V rows into s_v ----
            {
                const float* src = in + (size_t)(b * CIN + ci) * S4
                                      + (size_t)(t0 + s) * S3;
                for (int rr = tid; rr < S2; rr += NTHR) {
                    const float* dp = src + rr * S;
                    float d[S];
#pragma unroll
                    for (int x = 0; x < S; x++) d[x] = dp[x];
                    float* vp = s_v + rr * VSTR;
#pragma unroll
                    for (int nt = 0; nt < NT; nt++) {
                        const float e0 = d[3*nt+0], e1 = d[3*nt+1], e2 = d[3*nt+2];
                        const float e3 = d[3*nt+3], e4 = d[3*nt+4], e5 = d[3*nt+5];
                        vp[nt*6+0] =  4.0f*e0 - 5.0f*e2 + e4;
                        vp[nt*6+1] = -4.0f*e1 - 4.0f*e2 + e3 + e4;
                        vp[nt*6+2] =  4.0f*e1 - 4.0f*e2 - e3 + e4;
                        vp[nt*6+3] = -2.0f*e1 -      e2 + 2.0f*e3 + e4;
                        vp[nt*6+4] =  2.0f*e1 -      e2 - 2.0f*e3 + e4;
                        vp[nt*6+5] =  4.0f*e1 - 5.0f*e3 + e5;
                    }
                }
            }
            __syncthreads();

            const int kt = s - tl;
            if (act && kt >= 0 && kt < K) {
#pragma unroll 1
                for (int kd = 0; kd < K; kd++) {
#pragma unroll
                    for (int kh = 0; kh < K; kh++) {
                        const int rr = (dd + kd) * S + (hh + kh);
                        const float* vp = s_v + rr * VSTR;
                        const int tap = ((ci * K + kt) * K + kd) * K + kh;
                        const float* up = s_u + (size_t)(tap * COUT) * 6;
#pragma unroll
                        for (int nt = 0; nt < NT; nt++) {
                            const float V0 = vp[nt*6+0], V1 = vp[nt*6+1];
                            const float V2 = vp[nt*6+2], V3 = vp[nt*6+3];
                            const float V4 = vp[nt*6+4], V5 = vp[nt*6+5];
#pragma unroll
                            for (int co = 0; co < COUT; co++) {
                                const float* u = up + co * 6;
                                m[co][nt][0] = fmaf(u[0], V0, m[co][nt][0]);
                                m[co][nt][1] = fmaf(u[1], V1, m[co][nt][1]);
                                m[co][nt][2] = fmaf(u[2], V2, m[co][nt][2]);
                                m[co][nt][3] = fmaf(u[3], V3, m[co][nt][3]);
                                m[co][nt][4] = fmaf(u[4], V4, m[co][nt][4]);
                                m[co][nt][5] = fmaf(u[5], V5, m[co][nt][5]);
                            }
                        }
                    }
                }
            }
        }
    }

    // ---- output transform y = G^T m, bias + ReLU, store ----
    if (act) {
        const int t = t0 + tl;
        constexpr float c6 = 1.0f / 6.0f, c12 = 1.0f / 12.0f, c24 = 1.0f / 24.0f;
#pragma unroll
        for (int co = 0; co < COUT; co++) {
            const float bv = bias[co];
            float* op = out + (size_t)(b * COUT + co) * ((size_t)O * O3)
                            + (size_t)t * O3 + (dd * O + hh) * O;
#pragma unroll
            for (int nt = 0; nt < NT; nt++) {
                const float q0 = m[co][nt][0], q1 = m[co][nt][1], q2 = m[co][nt][2];
                const float q3 = m[co][nt][3], q4 = m[co][nt][4], q5 = m[co][nt][5];
                const float a12 = q1 + q2, p34 = q3 + q4;
                const float y0 = 0.25f * q0 - c6 * a12 + c24 * p34;
                const float y1 = c6 * (q2 - q1) + c12 * (q3 - q4);
                const float y2 = -c6 * a12 + c6 * p34 + q5;
                op[3*nt + 0] = fmaxf(y0 + bv, 0.0f);
                op[3*nt + 1] = fmaxf(y1 + bv, 0.0f);
                op[3*nt + 2] = fmaxf(y2 + bv, 0.0f);
            }
        }
    }
}

// ===========================================================================
// convS: R1's proven full-row scalar conv (+bias+ReLU) — used for L5.
// ===========================================================================
template<int CIN, int COUT, int K, int S, int TLOC, int NTHR>
__global__ void __launch_bounds__(NTHR)
convS(const float* __restrict__ in, float* __restrict__ out,
      const float* __restrict__ w, const float* __restrict__ bias)
{
    constexpr int O = S - K + 1, TCH = O / TLOC, NST = TLOC + K - 1;
    constexpr int S2 = S * S, S3 = S2 * S, S4 = S3 * S;
    constexpr int O2 = O * O, O3 = O2 * O;
    constexpr int KW4 = K * K * K * K;
    constexpr int NW = COUT * CIN * KW4;
    constexpr int NACT = TLOC * O2;

    __shared__ float s_slice[S3];
    __shared__ float s_w[NW];

    const int bt = blockIdx.x, tchunk = bt % TCH, b = bt / TCH;
    const int t0 = tchunk * TLOC, tid = threadIdx.x;

    for (int i = tid; i < NW; i += NTHR) s_w[i] = w[i];

    const int tl = tid / O2, rem = tid - tl * O2, dd = rem / O, hh = rem - dd * O;
    const bool act = tid < NACT;

    float acc[COUT][O];
#pragma unroll
    for (int c = 0; c < COUT; c++)
#pragma unroll
        for (int r = 0; r < O; r++) acc[c][r] = 0.0f;

#pragma unroll 1
    for (int ci = 0; ci < CIN; ci++) {
#pragma unroll 1
        for (int s = 0; s < NST; s++) {
            __syncthreads();
            const float* src = in + (size_t)(b * CIN + ci) * S4 + (size_t)(t0 + s) * S3;
            for (int i = tid; i < S3; i += NTHR) s_slice[i] = src[i];
            __syncthreads();

            const int kt = s - tl;
            if (act && kt >= 0 && kt < K) {
                const float* wb = s_w + (ci * K + kt) * (K * K * K);
#pragma unroll 1
                for (int kd = 0; kd < K; kd++) {
#pragma unroll
                    for (int kh = 0; kh < K; kh++) {
                        const float* rp = s_slice + (dd + kd) * S2 + (hh + kh) * S;
                        float row[S];
#pragma unroll
                        for (int x = 0; x < S; x++) row[x] = rp[x];

                        float wr[COUT][K];
#pragma unroll
                        for (int co = 0; co < COUT; co++)
#pragma unroll
                            for (int kw = 0; kw < K; kw++)
                                wr[co][kw] = wb[co * CIN * KW4 + (kd * K + kh) * K + kw];

#pragma unroll
                        for (int kw = 0; kw < K; kw++)
#pragma unroll
                            for (int r = 0; r < O; r++)
#pragma unroll
                                for (int co = 0; co < COUT; co++)
                                    acc[co][r] = fmaf(wr[co][kw], row[r + kw], acc[co][r]);
                    }
                }
            }
        }
    }

    if (act) {
        const int t = t0 + tl;
#pragma unroll
        for (int co = 0; co < COUT; co++) {
            const float bv = bias[co];
            float* op = out + (size_t)(b * COUT + co) * ((size_t)O * O3)
                            + (size_t)t * O3 + (dd * O + hh) * O;
#pragma unroll
            for (int r = 0; r < O; r++)
                op[r] = fmaxf(acc[co][r] + bv, 0.0f);
        }
    }
}

// ===========================================================================
// convB (measured-fastest L4, unchanged)
// ===========================================================================
template<int CO, int K, int RP, int COS>
__device__ __forceinline__ void row_r2(const float* __restrict__ rsrc,
                                       const float* __restrict__ wq,
                                       ull (&acc)[CO][RP])
{
    constexpr int RL = 2 * RP + K - 1;
    float row[RL];
#pragma unroll
    for (int x = 0; x < RL; x++) row[x] = rsrc[x];

    constexpr int NE = RP + 1;
    constexpr int NO = RP + (K >= 4 ? 1 : 0);
    ull rowE[NE], rowO[NO];
#pragma unroll
    for (int j = 0; j < NE; j++) rowE[j] = pk2(row[2 * j], row[2 * j + 1]);
#pragma unroll
    for (int j = 0; j < NO; j++) rowO[j] = pk2(row[2 * j + 1], row[2 * j + 2]);

#pragma unroll
    for (int kw = 0; kw < K; kw++) {
#pragma unroll
        for (int co = 0; co < CO; co++) {
            const float wv = wq[co * COS + kw];
            const ull w2 = pk2(wv, wv);
#pragma unroll
            for (int j = 0; j < RP; j++) {
                const ull a = (kw & 1) ? rowO[(kw >> 1) + j] : rowE[(kw >> 1) + j];
                fma2(acc[co][j], a, w2);
            }
        }
    }
}

template<int CIN, int COUT, int K, int S, int NTHR>
__global__ void __launch_bounds__(NTHR)
convB(const float* __restrict__ in, float* __restrict__ out,
      const float* __restrict__ w, const float* __restrict__ bias)
{
    constexpr int O = S - K + 1;
    constexpr int S2 = S * S, S3 = S2 * S, S4 = S3 * S;
    constexpr int O2 = O * O, O3 = O2 * O, O4 = O * O3;
    constexpr int K4 = K * K * K * K, NW = COUT * CIN * K4;
    constexpr int NACT = O * O2;
    constexpr int RP = (O + 1) / 2;
    constexpr int VP = slice_pitch(S4);

    extern __shared__ float dsm[];           // 2 * VP
    __shared__ float s_w[NW];

    const int b = blockIdx.x, tid = threadIdx.x;
    for (int i = tid; i < NW; i += NTHR) s_w[i] = w[i];

    const int tl = tid / O2, rem = tid - tl * O2, dd = rem / O, hh = rem - dd * O;
    const bool act = tid < NACT;

    ull acc[COUT][RP];
#pragma unroll
    for (int c = 0; c < COUT; c++)
#pragma unroll
        for (int j = 0; j < RP; j++) acc[c][j] = 0ull;

    {
        const float* src = in + (size_t)b * CIN * S4;
        for (int i = tid; i < S4; i += NTHR) dsm[i] = src[i];
    }
#pragma unroll 1
    for (int ci = 0; ci < CIN; ci++) {
        __syncthreads();
        if (ci + 1 < CIN) {
            const float* src = in + ((size_t)b * CIN + ci + 1) * S4;
            float* dst = dsm + ((ci + 1) & 1) * VP;
            for (int i = tid; i < S4; i += NTHR) dst[i] = src[i];
        }
        if (act) {
            const float* buf = dsm + (ci & 1) * VP;
#pragma unroll 1
            for (int kt = 0; kt < K; kt++) {
#pragma unroll 1
                for (int kd = 0; kd < K; kd++) {
#pragma unroll
                    for (int kh = 0; kh < K; kh++) {
                        const float* rp_ = buf + (tl + kt) * S3 + (dd + kd) * S2 + (hh + kh) * S;
                        const float* wq  = s_w + (((ci * K + kt) * K + kd) * K + kh) * K;
                        row_r2<COUT, K, RP, CIN * K4>(rp_, wq, acc);
                    }
                }
            }
        }
    }

    if (act) {
#pragma unroll
        for (int co = 0; co < COUT; co++) {
            const float bv = bias[co];
            float* op = out + ((size_t)b * COUT + co) * (size_t)O4
                            + (size_t)tl * O3 + (dd * O + hh) * O;
#pragma unroll
            for (int j = 0; j < RP; j++) {
                float v0, v1; upk2(acc[co][j], v0, v1);
                op[2 * j] = fmaxf(v0 + bv, 0.0f);
                if (2 * j + 1 < O) op[2 * j + 1] = fmaxf(v1 + bv, 0.0f);
            }
        }
    }
}

// ---------------------------------------------------------------------------
// Fused FC1(1280->33) + ReLU + FC2(33->1) + sigmoid. One block per batch row.
// ---------------------------------------------------------------------------
__global__ void __launch_bounds__(64)
fc_head(const float* __restrict__ h,
        const float* __restrict__ fc1w, const float* __restrict__ fc1b,
        const float* __restrict__ fc2w, const float* __restrict__ fc2b,
        float* __restrict__ out)
{
    __shared__ float sh[1280];
    __shared__ float so[33];
    const int b = blockIdx.x;

    for (int i = threadIdx.x; i < 1280; i += 64) sh[i] = h[(size_t)b * 1280 + i];
    __syncthreads();

    const int co = threadIdx.x;
    if (co < 33) {
        float a = 0.0f;
        const float* wr = fc1w + co * 1280;
#pragma unroll 4
        for (int k = 0; k < 1280; k++) a = fmaf(sh[k], __ldg(&wr[k]), a);
        so[co] = fmaxf(a + fc1b[co], 0.0f);
    }
    __syncthreads();

    if (threadIdx.x == 0) {
        float z = fc2b[0];
#pragma unroll
        for (int j = 0; j < 33; j++) z = fmaf(so[j], __ldg(&fc2w[j]), z);
        out[b] = 1.0f / (1.0f + expf(-z));
    }
}

// ---------------------------------------------------------------------------
// Inputs (metadata order):
// 0:x 1:w1 2:b1 3:w2 4:b2 5:w3 6:b3 7:w4 8:b4 9:w5 10:b5
// 11:fc1_w 12:fc1_b 13:fc2_w 14:fc2_b    -> out: [B,1] float32
// ---------------------------------------------------------------------------
extern "C" void kernel_launch(void* const* d_in, const int* in_sizes, int n_in,
                              void* d_out, int out_size)
{
    const float* x   = (const float*)d_in[0];
    const float* w1  = (const float*)d_in[1];
    const float* b1  = (const float*)d_in[2];
    const float* w2  = (const float*)d_in[3];
    const float* b2  = (const float*)d_in[4];
    const float* w3  = (const float*)d_in[5];
    const float* b3  = (const float*)d_in[6];
    const float* w4  = (const float*)d_in[7];
    const float* b4  = (const float*)d_in[8];
    const float* w5  = (const float*)d_in[9];
    const float* b5  = (const float*)d_in[10];
    const float* f1w = (const float*)d_in[11];
    const float* f1b = (const float*)d_in[12];
    const float* f2w = (const float*)d_in[13];
    const float* f2b = (const float*)d_in[14];

    const int B = in_sizes[0] / (18 * 18 * 18 * 18);

    float *a1, *a2, *a3, *a4, *a5;
    cudaGetSymbolAddress((void**)&a1, g_a1);
    cudaGetSymbolAddress((void**)&a2, g_a2);
    cudaGetSymbolAddress((void**)&a3, g_a3);
    cudaGetSymbolAddress((void**)&a4, g_a4);
    cudaGetSymbolAddress((void**)&a5, g_a5);

    constexpr int SM4 = 2 * slice_pitch(9 * 9 * 9 * 9) * 4;      // 52528 B

    cudaFuncSetAttribute(convB<4, 5, 4, 9, 224>,
                         cudaFuncAttributeMaxDynamicSharedMemorySize, SM4);

    // L1: 18^4 -> 15^4, 1->3, k=4   (Winograd-W: 5 tiles, 225/256 active)
    convW<1, 3, 4, 18, 1, 256, 2><<<B * 15, 256>>>(x,  a1, w1, b1);
    // L2: 15^4 -> 12^4, 3->3, k=4   (Winograd-W: 4 tiles, 144/256 active)
    convW<3, 3, 4, 15, 1, 256, 2><<<B * 12, 256>>>(a1, a2, w2, b2);
    // L3: 12^4 -> 9^4, 3->4, k=4    (Winograd-W: 3 tiles, TLOC=3, 243/256)
    convW<3, 4, 4, 12, 3, 256, 2><<<B * 3, 256>>>(a2, a3, w3, b3);
    // L4: 9^4 -> 6^4, 4->5, k=4     (convB, measured ~124us seven times)
    convB<4, 5, 4, 9, 224><<<B, 224, SM4>>>(a3, a4, w4, b4);
    // L5: 6^4 -> 4^4, 5->5, k=3     (scalar, O=4 not divisible by 3)
    convS<5, 5, 3, 6, 4, 128><<<B, 128>>>(a4, a5, w5, b5);
    // FC head: [B,1280] -> [B,33] -> [B,1] sigmoid
    fc_head<<<B, 64>>>(a5, f1w, f1b, f2w, f2b, (float*)d_out);
}

// round 14
// speedup vs baseline: 1.0159x; 1.0159x over previous
#include <cuda_runtime.h>
#include <math.h>

typedef unsigned long long ull;

// ---------------------------------------------------------------------------
// Packed f32x2 helpers (convB only — measured fastest for L4)
// ---------------------------------------------------------------------------
__device__ __forceinline__ ull pk2(float lo, float hi) {
    ull r; asm("mov.b64 %0, {%1, %2};" : "=l"(r) : "f"(lo), "f"(hi)); return r;
}
__device__ __forceinline__ void upk2(ull v, float& lo, float& hi) {
    asm("mov.b64 {%0, %1}, %2;" : "=f"(lo), "=f"(hi) : "l"(v));
}
__device__ __forceinline__ void fma2(ull& d, ull a, ull b) {
    asm("fma.rn.f32x2 %0, %1, %2, %0;" : "+l"(d) : "l"(a), "l"(b));
}

// ---------------------------------------------------------------------------
// Intermediate activation buffers (device globals — no allocation allowed).
// ---------------------------------------------------------------------------
__device__ float g_a1[38880000];   // 256*3*15^4
__device__ float g_a2[15925248];   // 256*3*12^4
__device__ float g_a3[6718464];    // 256*4*9^4
__device__ float g_a4[1658880];    // 256*5*6^4
__device__ float g_a5[327680];     // 256*5*4^4  (== flattened [256,1280])

__host__ __device__ constexpr int slice_pitch(int s3) { return (s3 + 6) & ~1; }

// ===========================================================================
// convW2: Winograd-F(3,4)-in-W conv (+bias+ReLU), K=4, O%3==0.
// vs R13 convW: (a) U is hoisted into registers ONCE per tap (no NT-fold
// re-reads from SMEM), (b) used only where acc regs fit (CO*NT*6 <= 72).
//   Per tap: 18 U-LDS + NT*6 V-LDS + CO*NT*6 FMA
//   (L2: 42 LDS + 72 FMA vs scalar 27 LDS + 144 FMA)
// ===========================================================================
template<int CIN, int COUT, int K, int S, int TLOC, int NTHR, int MINB>
__global__ void __launch_bounds__(NTHR, MINB)
convW2(const float* __restrict__ in, float* __restrict__ out,
       const float* __restrict__ w, const float* __restrict__ bias)
{
    static_assert(K == 4, "convW2 requires K=4");
    constexpr int O = S - K + 1;
    static_assert(O % 3 == 0, "convW2 requires O divisible by 3");
    constexpr int NT = O / 3;
    constexpr int TCH = O / TLOC, NST = TLOC + K - 1;
    constexpr int S2 = S * S, S3 = S2 * S, S4 = S3 * S;
    constexpr int O2 = O * O, O3 = O2 * O;
    constexpr int NACT = TLOC * O2;
    constexpr int VSTR = NT * 6 + 1;           // odd pitch -> conflict-free
    constexpr int NTAP = CIN * K * K * K;

    __shared__ float s_v[S2 * VSTR];
    __shared__ float s_u[NTAP * COUT * 6];

    const int bt = blockIdx.x, tch = bt % TCH, b = bt / TCH;
    const int t0 = tch * TLOC, tid = threadIdx.x;

    // ---- weight transform U = A·g, once per block ----
    for (int i = tid; i < NTAP * COUT; i += NTHR) {
        const int tap = i / COUT, co = i - tap * COUT;
        const int kh = tap % K;  const int r1 = tap / K;
        const int kd = r1 % K;   const int r2 = r1 / K;
        const int kt = r2 % K;   const int ci = r2 / K;
        const float* gp = w + ((((co * CIN + ci) * K + kt) * K + kd) * K + kh) * K;
        const float g0 = gp[0], g1 = gp[1], g2 = gp[2], g3 = gp[3];
        float* up = s_u + (size_t)i * 6;
        up[0] = g0;
        up[1] = g0 + g1 + g2 + g3;
        up[2] = g0 - g1 + g2 - g3;
        up[3] = g0 + 2.0f * g1 + 4.0f * g2 + 8.0f * g3;
        up[4] = g0 - 2.0f * g1 + 4.0f * g2 - 8.0f * g3;
        up[5] = g3;
    }

    const int tl = tid / O2, rem = tid - tl * O2, dd = rem / O, hh = rem - dd * O;
    const bool act = tid < NACT;

    float m[COUT][NT][6];
#pragma unroll
    for (int c = 0; c < COUT; c++)
#pragma unroll
        for (int nt = 0; nt < NT; nt++)
#pragma unroll
            for (int j = 0; j < 6; j++) m[c][nt][j] = 0.0f;

#pragma unroll 1
    for (int ci = 0; ci < CIN; ci++) {
#pragma unroll 1
        for (int s = 0; s < NST; s++) {
            __syncthreads();
            {   // stage + input transform (V = B^T d per W-row)
                const float* src = in + (size_t)(b * CIN + ci) * S4
                                      + (size_t)(t0 + s) * S3;
                for (int rr = tid; rr < S2; rr += NTHR) {
                    const float* dp = src + rr * S;
                    float* vp = s_v + rr * VSTR;
#pragma unroll
                    for (int nt = 0; nt < NT; nt++) {
                        const float e0 = dp[3*nt+0], e1 = dp[3*nt+1], e2 = dp[3*nt+2];
                        const float e3 = dp[3*nt+3], e4 = dp[3*nt+4], e5 = dp[3*nt+5];
                        vp[nt*6+0] =  4.0f*e0 - 5.0f*e2 + e4;
                        vp[nt*6+1] = -4.0f*e1 - 4.0f*e2 + e3 + e4;
                        vp[nt*6+2] =  4.0f*e1 - 4.0f*e2 - e3 + e4;
                        vp[nt*6+3] = -2.0f*e1 -      e2 + 2.0f*e3 + e4;
                        vp[nt*6+4] =  2.0f*e1 -      e2 - 2.0f*e3 + e4;
                        vp[nt*6+5] =  4.0f*e1 - 5.0f*e3 + e5;
                    }
                }
            }
            __syncthreads();

            const int kt = s - tl;
            if (act && kt >= 0 && kt < K) {
#pragma unroll 1
                for (int kd = 0; kd < K; kd++) {
#pragma unroll
                    for (int kh = 0; kh < K; kh++) {
                        const int rr = (dd + kd) * S + (hh + kh);
                        const float* vp = s_v + rr * VSTR;
                        const int tap = ((ci * K + kt) * K + kd) * K + kh;
                        const float* up = s_u + (size_t)(tap * COUT) * 6;

                        // hoist ALL U for this tap into registers (once)
                        float u[COUT][6];
#pragma unroll
                        for (int co = 0; co < COUT; co++)
#pragma unroll
                            for (int j = 0; j < 6; j++)
                                u[co][j] = up[co * 6 + j];

#pragma unroll
                        for (int nt = 0; nt < NT; nt++) {
                            const float V0 = vp[nt*6+0], V1 = vp[nt*6+1];
                            const float V2 = vp[nt*6+2], V3 = vp[nt*6+3];
                            const float V4 = vp[nt*6+4], V5 = vp[nt*6+5];
#pragma unroll
                            for (int co = 0; co < COUT; co++) {
                                m[co][nt][0] = fmaf(u[co][0], V0, m[co][nt][0]);
                                m[co][nt][1] = fmaf(u[co][1], V1, m[co][nt][1]);
                                m[co][nt][2] = fmaf(u[co][2], V2, m[co][nt][2]);
                                m[co][nt][3] = fmaf(u[co][3], V3, m[co][nt][3]);
                                m[co][nt][4] = fmaf(u[co][4], V4, m[co][nt][4]);
                                m[co][nt][5] = fmaf(u[co][5], V5, m[co][nt][5]);
                            }
                        }
                    }
                }
            }
        }
    }

    if (act) {
        const int t = t0 + tl;
        constexpr float c6 = 1.0f / 6.0f, c12 = 1.0f / 12.0f, c24 = 1.0f / 24.0f;
#pragma unroll
        for (int co = 0; co < COUT; co++) {
            const float bv = bias[co];
            float* op = out + (size_t)(b * COUT + co) * ((size_t)O * O3)
                            + (size_t)t * O3 + (dd * O + hh) * O;
#pragma unroll
            for (int nt = 0; nt < NT; nt++) {
                const float q0 = m[co][nt][0], q1 = m[co][nt][1], q2 = m[co][nt][2];
                const float q3 = m[co][nt][3], q4 = m[co][nt][4], q5 = m[co][nt][5];
                const float a12 = q1 + q2, p34 = q3 + q4;
                const float y0 = 0.25f * q0 - c6 * a12 + c24 * p34;
                const float y1 = c6 * (q2 - q1) + c12 * (q3 - q4);
                const float y2 = -c6 * a12 + c6 * p34 + q5;
                op[3*nt + 0] = fmaxf(y0 + bv, 0.0f);
                op[3*nt + 1] = fmaxf(y1 + bv, 0.0f);
                op[3*nt + 2] = fmaxf(y2 + bv, 0.0f);
            }
        }
    }
}

// ===========================================================================
// convS: R1's proven full-row scalar conv (+bias+ReLU) — L1 and L5.
// ===========================================================================
template<int CIN, int COUT, int K, int S, int TLOC, int NTHR>
__global__ void __launch_bounds__(NTHR)
convS(const float* __restrict__ in, float* __restrict__ out,
      const float* __restrict__ w, const float* __restrict__ bias)
{
    constexpr int O = S - K + 1, TCH = O / TLOC, NST = TLOC + K - 1;
    constexpr int S2 = S * S, S3 = S2 * S, S4 = S3 * S;
    constexpr int O2 = O * O, O3 = O2 * O;
    constexpr int KW4 = K * K * K * K;
    constexpr int NW = COUT * CIN * KW4;
    constexpr int NACT = TLOC * O2;

    __shared__ float s_slice[S3];
    __shared__ float s_w[NW];

    const int bt = blockIdx.x, tchunk = bt % TCH, b = bt / TCH;
    const int t0 = tchunk * TLOC, tid = threadIdx.x;

    for (int i = tid; i < NW; i += NTHR) s_w[i] = w[i];

    const int tl = tid / O2, rem = tid - tl * O2, dd = rem / O, hh = rem - dd * O;
    const bool act = tid < NACT;

    float acc[COUT][O];
#pragma unroll
    for (int c = 0; c < COUT; c++)
#pragma unroll
        for (int r = 0; r < O; r++) acc[c][r] = 0.0f;

#pragma unroll 1
    for (int ci = 0; ci < CIN; ci++) {
#pragma unroll 1
        for (int s = 0; s < NST; s++) {
            __syncthreads();
            const float* src = in + (size_t)(b * CIN + ci) * S4 + (size_t)(t0 + s) * S3;
            for (int i = tid; i < S3; i += NTHR) s_slice[i] = src[i];
            __syncthreads();

            const int kt = s - tl;
            if (act && kt >= 0 && kt < K) {
                const float* wb = s_w + (ci * K + kt) * (K * K * K);
#pragma unroll 1
                for (int kd = 0; kd < K; kd++) {
#pragma unroll
                    for (int kh = 0; kh < K; kh++) {
                        const float* rp = s_slice + (dd + kd) * S2 + (hh + kh) * S;
                        float row[S];
#pragma unroll
                        for (int x = 0; x < S; x++) row[x] = rp[x];

                        float wr[COUT][K];
#pragma unroll
                        for (int co = 0; co < COUT; co++)
#pragma unroll
                            for (int kw = 0; kw < K; kw++)
                                wr[co][kw] = wb[co * CIN * KW4 + (kd * K + kh) * K + kw];

#pragma unroll
                        for (int kw = 0; kw < K; kw++)
#pragma unroll
                            for (int r = 0; r < O; r++)
#pragma unroll
                                for (int co = 0; co < COUT; co++)
                                    acc[co][r] = fmaf(wr[co][kw], row[r + kw], acc[co][r]);
                    }
                }
            }
        }
    }

    if (act) {
        const int t = t0 + tl;
#pragma unroll
        for (int co = 0; co < COUT; co++) {
            const float bv = bias[co];
            float* op = out + (size_t)(b * COUT + co) * ((size_t)O * O3)
                            + (size_t)t * O3 + (dd * O + hh) * O;
#pragma unroll
            for (int r = 0; r < O; r++)
                op[r] = fmaxf(acc[co][r] + bv, 0.0f);
        }
    }
}

// ===========================================================================
// convB (measured-fastest L4, unchanged)
// ===========================================================================
template<int CO, int K, int RP, int COS>
__device__ __forceinline__ void row_r2(const float* __restrict__ rsrc,
                                       const float* __restrict__ wq,
                                       ull (&acc)[CO][RP])
{
    constexpr int RL = 2 * RP + K - 1;
    float row[RL];
#pragma unroll
    for (int x = 0; x < RL; x++) row[x] = rsrc[x];

    constexpr int NE = RP + 1;
    constexpr int NO = RP + (K >= 4 ? 1 : 0);
    ull rowE[NE], rowO[NO];
#pragma unroll
    for (int j = 0; j < NE; j++) rowE[j] = pk2(row[2 * j], row[2 * j + 1]);
#pragma unroll
    for (int j = 0; j < NO; j++) rowO[j] = pk2(row[2 * j + 1], row[2 * j + 2]);

#pragma unroll
    for (int kw = 0; kw < K; kw++) {
#pragma unroll
        for (int co = 0; co < CO; co++) {
            const float wv = wq[co * COS + kw];
            const ull w2 = pk2(wv, wv);
#pragma unroll
            for (int j = 0; j < RP; j++) {
                const ull a = (kw & 1) ? rowO[(kw >> 1) + j] : rowE[(kw >> 1) + j];
                fma2(acc[co][j], a, w2);
            }
        }
    }
}

template<int CIN, int COUT, int K, int S, int NTHR>
__global__ void __launch_bounds__(NTHR)
convB(const float* __restrict__ in, float* __restrict__ out,
      const float* __restrict__ w, const float* __restrict__ bias)
{
    constexpr int O = S - K + 1;
    constexpr int S2 = S * S, S3 = S2 * S, S4 = S3 * S;
    constexpr int O2 = O * O, O3 = O2 * O, O4 = O * O3;
    constexpr int K4 = K * K * K * K, NW = COUT * CIN * K4;
    constexpr int NACT = O * O2;
    constexpr int RP = (O + 1) / 2;
    constexpr int VP = slice_pitch(S4);

    extern __shared__ float dsm[];           // 2 * VP
    __shared__ float s_w[NW];

    const int b = blockIdx.x, tid = threadIdx.x;
    for (int i = tid; i < NW; i += NTHR) s_w[i] = w[i];

    const int tl = tid / O2, rem = tid - tl * O2, dd = rem / O, hh = rem - dd * O;
    const bool act = tid < NACT;

    ull acc[COUT][RP];
#pragma unroll
    for (int c = 0; c < COUT; c++)
#pragma unroll
        for (int j = 0; j < RP; j++) acc[c][j] = 0ull;

    {
        const float* src = in + (size_t)b * CIN * S4;
        for (int i = tid; i < S4; i += NTHR) dsm[i] = src[i];
    }
#pragma unroll 1
    for (int ci = 0; ci < CIN; ci++) {
        __syncthreads();
        if (ci + 1 < CIN) {
            const float* src = in + ((size_t)b * CIN + ci + 1) * S4;
            float* dst = dsm + ((ci + 1) & 1) * VP;
            for (int i = tid; i < S4; i += NTHR) dst[i] = src[i];
        }
        if (act) {
            const float* buf = dsm + (ci & 1) * VP;
#pragma unroll 1
            for (int kt = 0; kt < K; kt++) {
#pragma unroll 1
                for (int kd = 0; kd < K; kd++) {
#pragma unroll
                    for (int kh = 0; kh < K; kh++) {
                        const float* rp_ = buf + (tl + kt) * S3 + (dd + kd) * S2 + (hh + kh) * S;
                        const float* wq  = s_w + (((ci * K + kt) * K + kd) * K + kh) * K;
                        row_r2<COUT, K, RP, CIN * K4>(rp_, wq, acc);
                    }
                }
            }
        }
    }

    if (act) {
#pragma unroll
        for (int co = 0; co < COUT; co++) {
            const float bv = bias[co];
            float* op = out + ((size_t)b * COUT + co) * (size_t)O4
                            + (size_t)tl * O3 + (dd * O + hh) * O;
#pragma unroll
            for (int j = 0; j < RP; j++) {
                float v0, v1; upk2(acc[co][j], v0, v1);
                op[2 * j] = fmaxf(v0 + bv, 0.0f);
                if (2 * j + 1 < O) op[2 * j + 1] = fmaxf(v1 + bv, 0.0f);
            }
        }
    }
}

// ---------------------------------------------------------------------------
// Fused FC1(1280->33) + ReLU + FC2(33->1) + sigmoid. One block per batch row.
// ---------------------------------------------------------------------------
__global__ void __launch_bounds__(64)
fc_head(const float* __restrict__ h,
        const float* __restrict__ fc1w, const float* __restrict__ fc1b,
        const float* __restrict__ fc2w, const float* __restrict__ fc2b,
        float* __restrict__ out)
{
    __shared__ float sh[1280];
    __shared__ float so[33];
    const int b = blockIdx.x;

    for (int i = threadIdx.x; i < 1280; i += 64) sh[i] = h[(size_t)b * 1280 + i];
    __syncthreads();

    const int co = threadIdx.x;
    if (co < 33) {
        float a = 0.0f;
        const float* wr = fc1w + co * 1280;
#pragma unroll 4
        for (int k = 0; k < 1280; k++) a = fmaf(sh[k], __ldg(&wr[k]), a);
        so[co] = fmaxf(a + fc1b[co], 0.0f);
    }
    __syncthreads();

    if (threadIdx.x == 0) {
        float z = fc2b[0];
#pragma unroll
        for (int j = 0; j < 33; j++) z = fmaf(so[j], __ldg(&fc2w[j]), z);
        out[b] = 1.0f / (1.0f + expf(-z));
    }
}

// ---------------------------------------------------------------------------
// Inputs (metadata order):
// 0:x 1:w1 2:b1 3:w2 4:b2 5:w3 6:b3 7:w4 8:b4 9:w5 10:b5
// 11:fc1_w 12:fc1_b 13:fc2_w 14:fc2_b    -> out: [B,1] float32
// ---------------------------------------------------------------------------
extern "C" void kernel_launch(void* const* d_in, const int* in_sizes, int n_in,
                              void* d_out, int out_size)
{
    const float* x   = (const float*)d_in[0];
    const float* w1  = (const float*)d_in[1];
    const float* b1  = (const float*)d_in[2];
    const float* w2  = (const float*)d_in[3];
    const float* b2  = (const float*)d_in[4];
    const float* w3  = (const float*)d_in[5];
    const float* b3  = (const float*)d_in[6];
    const float* w4  = (const float*)d_in[7];
    const float* b4  = (const float*)d_in[8];
    const float* w5  = (const float*)d_in[9];
    const float* b5  = (const float*)d_in[10];
    const float* f1w = (const float*)d_in[11];
    const float* f1b = (const float*)d_in[12];
    const float* f2w = (const float*)d_in[13];
    const float* f2b = (const float*)d_in[14];

    const int B = in_sizes[0] / (18 * 18 * 18 * 18);

    float *a1, *a2, *a3, *a4, *a5;
    cudaGetSymbolAddress((void**)&a1, g_a1);
    cudaGetSymbolAddress((void**)&a2, g_a2);
    cudaGetSymbolAddress((void**)&a3, g_a3);
    cudaGetSymbolAddress((void**)&a4, g_a4);
    cudaGetSymbolAddress((void**)&a5, g_a5);

    constexpr int SM4 = 2 * slice_pitch(9 * 9 * 9 * 9) * 4;      // 52528 B

    cudaFuncSetAttribute(convB<4, 5, 4, 9, 224>,
                         cudaFuncAttributeMaxDynamicSharedMemorySize, SM4);

    // L1: 18^4 -> 15^4, 1->3, k=4   (scalar R12 exact — Winograd spills here)
    convS<1, 3, 4, 18, 1, 256><<<B * 15, 256>>>(x,  a1, w1, b1);
    // L2: 15^4 -> 12^4, 3->3, k=4   (Winograd v2: 72 accs fit, U hoisted)
    convW2<3, 3, 4, 15, 1, 256, 2><<<B * 12, 256>>>(a1, a2, w2, b2);
    // L3: 12^4 -> 9^4, 3->4, k=4    (Winograd v2: 72 accs fit, U hoisted)
    convW2<3, 4, 4, 12, 3, 256, 2><<<B * 3, 256>>>(a2, a3, w3, b3);
    // L4: 9^4 -> 6^4, 4->5, k=4     (convB, ~124us, eight measurements)
    convB<4, 5, 4, 9, 224><<<B, 224, SM4>>>(a3, a4, w4, b4);
    // L5: 6^4 -> 4^4, 5->5, k=3     (scalar R12 exact)
    convS<5, 5, 3, 6, 4, 128><<<B, 128>>>(a4, a5, w5, b5);
    // FC head: [B,1280] -> [B,33] -> [B,1] sigmoid
    fc_head<<<B, 64>>>(a5, f1w, f1b, f2w, f2b, (float*)d_out);
}

// round 15
// speedup vs baseline: 1.0633x; 1.0467x over previous
#include <cuda_runtime.h>
#include <math.h>

typedef unsigned long long ull;

// ---------------------------------------------------------------------------
// Packed f32x2 helpers (convB only — measured fastest for L4)
// ---------------------------------------------------------------------------
__device__ __forceinline__ ull pk2(float lo, float hi) {
    ull r; asm("mov.b64 %0, {%1, %2};" : "=l"(r) : "f"(lo), "f"(hi)); return r;
}
__device__ __forceinline__ void upk2(ull v, float& lo, float& hi) {
    asm("mov.b64 {%0, %1}, %2;" : "=f"(lo), "=f"(hi) : "l"(v));
}
__device__ __forceinline__ void fma2(ull& d, ull a, ull b) {
    asm("fma.rn.f32x2 %0, %1, %2, %0;" : "+l"(d) : "l"(a), "l"(b));
}

// ---------------------------------------------------------------------------
// Intermediate activation buffers (device globals — no allocation allowed).
// ---------------------------------------------------------------------------
__device__ float g_a1[38880000];   // 256*3*15^4
__device__ float g_a2[15925248];   // 256*3*12^4
__device__ float g_a3[6718464];    // 256*4*9^4
__device__ float g_a4[1658880];    // 256*5*6^4
__device__ float g_a5[327680];     // 256*5*4^4  (== flattened [256,1280])

__host__ __device__ constexpr int slice_pitch(int s3) { return (s3 + 6) & ~1; }

// ===========================================================================
// convS: R1's proven full-row scalar conv (+bias+ReLU). Block = (b, t-chunk).
// Thread = (t_local, d, h) computes the full W row for all COUT.
// MINB sets the ptxas reg cap = 65536/(NTHR*MINB); MINB=0 -> default bounds.
// ===========================================================================
template<int CIN, int COUT, int K, int S, int TLOC, int NTHR, int MINB>
__global__ void __launch_bounds__(NTHR, MINB)
convS(const float* __restrict__ in, float* __restrict__ out,
      const float* __restrict__ w, const float* __restrict__ bias)
{
    constexpr int O = S - K + 1, TCH = O / TLOC, NST = TLOC + K - 1;
    constexpr int S2 = S * S, S3 = S2 * S, S4 = S3 * S;
    constexpr int O2 = O * O, O3 = O2 * O;
    constexpr int KW4 = K * K * K * K;
    constexpr int NW = COUT * CIN * KW4;
    constexpr int NACT = TLOC * O2;

    __shared__ float s_slice[S3];
    __shared__ float s_w[NW];

    const int bt = blockIdx.x, tchunk = bt % TCH, b = bt / TCH;
    const int t0 = tchunk * TLOC, tid = threadIdx.x;

    for (int i = tid; i < NW; i += NTHR) s_w[i] = w[i];

    const int tl = tid / O2, rem = tid - tl * O2, dd = rem / O, hh = rem - dd * O;
    const bool act = tid < NACT;

    float acc[COUT][O];
#pragma unroll
    for (int c = 0; c < COUT; c++)
#pragma unroll
        for (int r = 0; r < O; r++) acc[c][r] = 0.0f;

#pragma unroll 1
    for (int ci = 0; ci < CIN; ci++) {
#pragma unroll 1
        for (int s = 0; s < NST; s++) {
            __syncthreads();
            const float* src = in + (size_t)(b * CIN + ci) * S4 + (size_t)(t0 + s) * S3;
            for (int i = tid; i < S3; i += NTHR) s_slice[i] = src[i];
            __syncthreads();

            const int kt = s - tl;
            if (act && kt >= 0 && kt < K) {
                const float* wb = s_w + (ci * K + kt) * (K * K * K);
#pragma unroll 1
                for (int kd = 0; kd < K; kd++) {
#pragma unroll
                    for (int kh = 0; kh < K; kh++) {
                        const float* rp = s_slice + (dd + kd) * S2 + (hh + kh) * S;
                        float row[S];
#pragma unroll
                        for (int x = 0; x < S; x++) row[x] = rp[x];

                        float wr[COUT][K];
#pragma unroll
                        for (int co = 0; co < COUT; co++)
#pragma unroll
                            for (int kw = 0; kw < K; kw++)
                                wr[co][kw] = wb[co * CIN * KW4 + (kd * K + kh) * K + kw];

#pragma unroll
                        for (int kw = 0; kw < K; kw++)
#pragma unroll
                            for (int r = 0; r < O; r++)
#pragma unroll
                                for (int co = 0; co < COUT; co++)
                                    acc[co][r] = fmaf(wr[co][kw], row[r + kw], acc[co][r]);
                    }
                }
            }
        }
    }

    if (act) {
        const int t = t0 + tl;
#pragma unroll
        for (int co = 0; co < COUT; co++) {
            const float bv = bias[co];
            float* op = out + (size_t)(b * COUT + co) * ((size_t)O * O3)
                            + (size_t)t * O3 + (dd * O + hh) * O;
#pragma unroll
            for (int r = 0; r < O; r++)
                op[r] = fmaxf(acc[co][r] + bv, 0.0f);
        }
    }
}

// ===========================================================================
// convB (measured-fastest L4, unchanged): whole-volume FFMA2 conv, block = b,
// thread = (t,d,h), double-buffered channel staging.
// ===========================================================================
template<int CO, int K, int RP, int COS>
__device__ __forceinline__ void row_r2(const float* __restrict__ rsrc,
                                       const float* __restrict__ wq,
                                       ull (&acc)[CO][RP])
{
    constexpr int RL = 2 * RP + K - 1;
    float row[RL];
#pragma unroll
    for (int x = 0; x < RL; x++) row[x] = rsrc[x];

    constexpr int NE = RP + 1;
    constexpr int NO = RP + (K >= 4 ? 1 : 0);
    ull rowE[NE], rowO[NO];
#pragma unroll
    for (int j = 0; j < NE; j++) rowE[j] = pk2(row[2 * j], row[2 * j + 1]);
#pragma unroll
    for (int j = 0; j < NO; j++) rowO[j] = pk2(row[2 * j + 1], row[2 * j + 2]);

#pragma unroll
    for (int kw = 0; kw < K; kw++) {
#pragma unroll
        for (int co = 0; co < CO; co++) {
            const float wv = wq[co * COS + kw];
            const ull w2 = pk2(wv, wv);
#pragma unroll
            for (int j = 0; j < RP; j++) {
                const ull a = (kw & 1) ? rowO[(kw >> 1) + j] : rowE[(kw >> 1) + j];
                fma2(acc[co][j], a, w2);
            }
        }
    }
}

template<int CIN, int COUT, int K, int S, int NTHR>
__global__ void __launch_bounds__(NTHR)
convB(const float* __restrict__ in, float* __restrict__ out,
      const float* __restrict__ w, const float* __restrict__ bias)
{
    constexpr int O = S - K + 1;
    constexpr int S2 = S * S, S3 = S2 * S, S4 = S3 * S;
    constexpr int O2 = O * O, O3 = O2 * O, O4 = O * O3;
    constexpr int K4 = K * K * K * K, NW = COUT * CIN * K4;
    constexpr int NACT = O * O2;
    constexpr int RP = (O + 1) / 2;
    constexpr int VP = slice_pitch(S4);

    extern __shared__ float dsm[];           // 2 * VP
    __shared__ float s_w[NW];

    const int b = blockIdx.x, tid = threadIdx.x;
    for (int i = tid; i < NW; i += NTHR) s_w[i] = w[i];

    const int tl = tid / O2, rem = tid - tl * O2, dd = rem / O, hh = rem - dd * O;
    const bool act = tid < NACT;

    ull acc[COUT][RP];
#pragma unroll
    for (int c = 0; c < COUT; c++)
#pragma unroll
        for (int j = 0; j < RP; j++) acc[c][j] = 0ull;

    {
        const float* src = in + (size_t)b * CIN * S4;
        for (int i = tid; i < S4; i += NTHR) dsm[i] = src[i];
    }
#pragma unroll 1
    for (int ci = 0; ci < CIN; ci++) {
        __syncthreads();
        if (ci + 1 < CIN) {
            const float* src = in + ((size_t)b * CIN + ci + 1) * S4;
            float* dst = dsm + ((ci + 1) & 1) * VP;
            for (int i = tid; i < S4; i += NTHR) dst[i] = src[i];
        }
        if (act) {
            const float* buf = dsm + (ci & 1) * VP;
#pragma unroll 1
            for (int kt = 0; kt < K; kt++) {
#pragma unroll 1
                for (int kd = 0; kd < K; kd++) {
#pragma unroll
                    for (int kh = 0; kh < K; kh++) {
                        const float* rp_ = buf + (tl + kt) * S3 + (dd + kd) * S2 + (hh + kh) * S;
                        const float* wq  = s_w + (((ci * K + kt) * K + kd) * K + kh) * K;
                        row_r2<COUT, K, RP, CIN * K4>(rp_, wq, acc);
                    }
                }
            }
        }
    }

    if (act) {
#pragma unroll
        for (int co = 0; co < COUT; co++) {
            const float bv = bias[co];
            float* op = out + ((size_t)b * COUT + co) * (size_t)O4
                            + (size_t)tl * O3 + (dd * O + hh) * O;
#pragma unroll
            for (int j = 0; j < RP; j++) {
                float v0, v1; upk2(acc[co][j], v0, v1);
                op[2 * j] = fmaxf(v0 + bv, 0.0f);
                if (2 * j + 1 < O) op[2 * j + 1] = fmaxf(v1 + bv, 0.0f);
            }
        }
    }
}

// ---------------------------------------------------------------------------
// Fused FC1(1280->33) + ReLU + FC2(33->1) + sigmoid. One block per batch row.
// ---------------------------------------------------------------------------
__global__ void __launch_bounds__(64)
fc_head(const float* __restrict__ h,
        const float* __restrict__ fc1w, const float* __restrict__ fc1b,
        const float* __restrict__ fc2w, const float* __restrict__ fc2b,
        float* __restrict__ out)
{
    __shared__ float sh[1280];
    __shared__ float so[33];
    const int b = blockIdx.x;

    for (int i = threadIdx.x; i < 1280; i += 64) sh[i] = h[(size_t)b * 1280 + i];
    __syncthreads();

    const int co = threadIdx.x;
    if (co < 33) {
        float a = 0.0f;
        const float* wr = fc1w + co * 1280;
#pragma unroll 4
        for (int k = 0; k < 1280; k++) a = fmaf(sh[k], __ldg(&wr[k]), a);
        so[co] = fmaxf(a + fc1b[co], 0.0f);
    }
    __syncthreads();

    if (threadIdx.x == 0) {
        float z = fc2b[0];
#pragma unroll
        for (int j = 0; j < 33; j++) z = fmaf(so[j], __ldg(&fc2w[j]), z);
        out[b] = 1.0f / (1.0f + expf(-z));
    }
}

// ---------------------------------------------------------------------------
// Inputs (metadata order):
// 0:x 1:w1 2:b1 3:w2 4:b2 5:w3 6:b3 7:w4 8:b4 9:w5 10:b5
// 11:fc1_w 12:fc1_b 13:fc2_w 14:fc2_b    -> out: [B,1] float32
// ---------------------------------------------------------------------------
extern "C" void kernel_launch(void* const* d_in, const int* in_sizes, int n_in,
                              void* d_out, int out_size)
{
    const float* x   = (const float*)d_in[0];
    const float* w1  = (const float*)d_in[1];
    const float* b1  = (const float*)d_in[2];
    const float* w2  = (const float*)d_in[3];
    const float* b2  = (const float*)d_in[4];
    const float* w3  = (const float*)d_in[5];
    const float* b3  = (const float*)d_in[6];
    const float* w4  = (const float*)d_in[7];
    const float* b4  = (const float*)d_in[8];
    const float* w5  = (const float*)d_in[9];
    const float* b5  = (const float*)d_in[10];
    const float* f1w = (const float*)d_in[11];
    const float* f1b = (const float*)d_in[12];
    const float* f2w = (const float*)d_in[13];
    const float* f2b = (const float*)d_in[14];

    const int B = in_sizes[0] / (18 * 18 * 18 * 18);

    float *a1, *a2, *a3, *a4, *a5;
    cudaGetSymbolAddress((void**)&a1, g_a1);
    cudaGetSymbolAddress((void**)&a2, g_a2);
    cudaGetSymbolAddress((void**)&a3, g_a3);
    cudaGetSymbolAddress((void**)&a4, g_a4);
    cudaGetSymbolAddress((void**)&a5, g_a5);

    constexpr int SM4 = 2 * slice_pitch(9 * 9 * 9 * 9) * 4;      // 52528 B

    cudaFuncSetAttribute(convB<4, 5, 4, 9, 224>,
                         cudaFuncAttributeMaxDynamicSharedMemorySize, SM4);

    // L1: 18^4 -> 15^4, 1->3, k=4   (R12 exact: grid 3840, 225/256 active)
    convS<1, 3, 4, 18, 1, 256, 2><<<B * 15, 256>>>(x,  a1, w1, b1);
    // L2: 15^4 -> 12^4, 3->3, k=4   (THE ISOLATED CHANGE: 160 thr, 144 active
    //     = 90%; MINB=4 -> reg cap 102, scalar needs ~90 so NO spills (R7's
    //     failure was cap 81) -> 4 CTAs/SM = 18 active warps vs R12's 9,
    //     byte-identical inner loop)
    convS<3, 3, 4, 15, 1, 160, 4><<<B * 12, 160>>>(a1, a2, w2, b2);
    // L3: 12^4 -> 9^4, 3->4, k=4    (R12 exact: grid 768, 243/256 active)
    convS<3, 4, 4, 12, 3, 256, 2><<<B * 3, 256>>>(a2, a3, w3, b3);
    // L4: 9^4 -> 6^4, 4->5, k=4     (convB, ~124us, nine measurements)
    convB<4, 5, 4, 9, 224><<<B, 224, SM4>>>(a3, a4, w4, b4);
    // L5: 6^4 -> 4^4, 5->5, k=3     (R12 exact)
    convS<5, 5, 3, 6, 4, 128, 2><<<B, 128>>>(a4, a5, w5, b5);
    // FC head: [B,1280] -> [B,33] -> [B,1] sigmoid
    fc_head<<<B, 64>>>(a5, f1w, f1b, f2w, f2b, (float*)d_out);
}